// round 4
// baseline (speedup 1.0000x reference)
#include <cuda_runtime.h>
#include <cuda_bf16.h>
#include <cstdint>

// Problem constants
#define NN 50000
#define EE 600000
#define DD 128
#define HH 128
#define CC 64
#define LLAYERS 3
#define XCW (DD + LLAYERS * HH)   // 512

// ---------------- scratch (device globals; no runtime allocation) ----------
__device__ int   g_hist[NN];
__device__ int   g_rowptr[NN + 1];
__device__ int   g_cursor[NN];
__device__ int   g_csr_src[EE];
__device__ float g_dinv[NN];
__device__ float g_hW[(size_t)NN * HH];     // holds u = dinv * (h @ W)
__device__ float g_xc[(size_t)NN * XCW];
__device__ float g_z[(size_t)NN * HH];
__device__ float g_z2[(size_t)NN * CC];

// ---------------- CSR build --------------------------------------------------
__global__ void k_zero_hist() {
    int i = blockIdx.x * blockDim.x + threadIdx.x;
    if (i < NN) g_hist[i] = 0;
}

__global__ void k_hist(const int* __restrict__ ei) {
    int e = blockIdx.x * blockDim.x + threadIdx.x;
    if (e < EE) atomicAdd(&g_hist[ei[EE + e]], 1);
}

// single-block exclusive scan over g_hist -> g_rowptr / g_cursor; also dinv
__global__ __launch_bounds__(1024) void k_scan() {
    const int CH = (NN + 1023) / 1024;   // 49
    int tid = threadIdx.x;
    int lane = tid & 31;
    int wid = tid >> 5;
    int beg = tid * CH;
    int end = min(beg + CH, NN);

    int s = 0;
    for (int i = beg; i < end; i++) s += g_hist[i];

    int v = s;
    #pragma unroll
    for (int o = 1; o < 32; o <<= 1) {
        int t = __shfl_up_sync(0xffffffffu, v, o);
        if (lane >= o) v += t;
    }
    __shared__ int ws[32];
    if (lane == 31) ws[wid] = v;
    __syncthreads();
    if (wid == 0) {
        int w = ws[lane];
        #pragma unroll
        for (int o = 1; o < 32; o <<= 1) {
            int t = __shfl_up_sync(0xffffffffu, w, o);
            if (lane >= o) w += t;
        }
        ws[lane] = w;
    }
    __syncthreads();
    int base = (wid ? ws[wid - 1] : 0) + v - s;   // exclusive offset
    for (int i = beg; i < end; i++) {
        g_rowptr[i] = base;
        g_cursor[i] = base;
        base += g_hist[i];
        g_dinv[i] = rsqrtf((float)(g_hist[i] + 1));
    }
    if (tid == 1023) g_rowptr[NN] = EE;
}

__global__ void k_fill(const int* __restrict__ ei) {
    int e = blockIdx.x * blockDim.x + threadIdx.x;
    if (e >= EE) return;
    int d = ei[EE + e];
    int pos = atomicAdd(&g_cursor[d], 1);
    g_csr_src[pos] = ei[e];
}

// ---------------- misc -------------------------------------------------------
__global__ void k_copy_x(const float* __restrict__ x) {
    int idx = blockIdx.x * blockDim.x + threadIdx.x;   // float4 index
    if (idx >= NN * 32) return;
    int n = idx >> 5;
    int c = idx & 31;
    ((float4*)g_xc)[(size_t)n * (XCW / 4) + c] = ((const float4*)x)[idx];
}

// fused: warp per node d — acc = u[d] + sum_{s in N(d)} u[s]; agg = dinv[d]*acc;
// then +bias, LayerNorm, ReLU -> xc[:, (1+layer)*128...]
__global__ void k_gather_ln(const float* __restrict__ bg,
                            const float* __restrict__ lng,
                            const float* __restrict__ lnb,
                            int layer) {
    int t = blockIdx.x * blockDim.x + threadIdx.x;
    int w = t >> 5;
    if (w >= NN) return;
    int lane = t & 31;

    float4 acc = ((const float4*)(g_hW + (size_t)w * HH))[lane];   // self (u[d])
    int pos = g_rowptr[w];
    int end = g_rowptr[w + 1];
    while (pos < end) {
        int n = min(32, end - pos);
        int eid = 0;
        if (lane < n) eid = g_csr_src[pos + lane];
        for (int j = 0; j < n; j++) {
            int s = __shfl_sync(0xffffffffu, eid, j);
            float4 v = ((const float4*)(g_hW + (size_t)s * HH))[lane];
            acc.x += v.x; acc.y += v.y; acc.z += v.z; acc.w += v.w;
        }
        pos += n;
    }
    float dd = g_dinv[w];
    float4 bb = ((const float4*)(bg + layer * HH))[lane];
    acc.x = fmaf(acc.x, dd, bb.x);
    acc.y = fmaf(acc.y, dd, bb.y);
    acc.z = fmaf(acc.z, dd, bb.z);
    acc.w = fmaf(acc.w, dd, bb.w);

    float s = acc.x + acc.y + acc.z + acc.w;
    #pragma unroll
    for (int o = 16; o; o >>= 1) s += __shfl_xor_sync(0xffffffffu, s, o);
    float mu = s * (1.0f / HH);

    float dx = acc.x - mu, dy = acc.y - mu, dz = acc.z - mu, dw = acc.w - mu;
    float q = dx * dx + dy * dy + dz * dz + dw * dw;
    #pragma unroll
    for (int o = 16; o; o >>= 1) q += __shfl_xor_sync(0xffffffffu, q, o);
    float inv = rsqrtf(q * (1.0f / HH) + 1e-5f);

    float4 g4 = ((const float4*)(lng + layer * HH))[lane];
    float4 b4 = ((const float4*)(lnb + layer * HH))[lane];
    float4 o4;
    o4.x = fmaxf(fmaf(g4.x * dx, inv, b4.x), 0.0f);
    o4.y = fmaxf(fmaf(g4.y * dy, inv, b4.y), 0.0f);
    o4.z = fmaxf(fmaf(g4.z * dz, inv, b4.z), 0.0f);
    o4.w = fmaxf(fmaf(g4.w * dw, inv, b4.w), 0.0f);
    ((float4*)g_xc)[(size_t)w * (XCW / 4) + (1 + layer) * 32 + lane] = o4;
}

// one warp per node: softmax over 64 (2 cols/thread)
__global__ void k_softmax(float* __restrict__ out) {
    int t = blockIdx.x * blockDim.x + threadIdx.x;
    int w = t >> 5;
    if (w >= NN) return;
    int lane = t & 31;
    float2 v = ((const float2*)g_z2)[(size_t)w * 32 + lane];
    float m = fmaxf(v.x, v.y);
    #pragma unroll
    for (int o = 16; o; o >>= 1) m = fmaxf(m, __shfl_xor_sync(0xffffffffu, m, o));
    float e0 = __expf(v.x - m);
    float e1 = __expf(v.y - m);
    float s = e0 + e1;
    #pragma unroll
    for (int o = 16; o; o >>= 1) s += __shfl_xor_sync(0xffffffffu, s, o);
    float inv = 1.0f / s;
    ((float2*)out)[(size_t)w * 32 + lane] = make_float2(e0 * inv, e1 * inv);
}

// ==================== bf16-split mma.sync GEMM ==============================
__device__ __forceinline__ uint32_t smem_u32(const void* p) {
    uint32_t a;
    asm("{ .reg .u64 t; cvta.to.shared.u64 t, %1; cvt.u32.u64 %0, t; }"
        : "=r"(a) : "l"(p));
    return a;
}

__device__ __forceinline__ void ldm_x4(uint32_t* r, uint32_t addr) {
    asm volatile("ldmatrix.sync.aligned.m8n8.x4.shared.b16 {%0,%1,%2,%3}, [%4];"
                 : "=r"(r[0]), "=r"(r[1]), "=r"(r[2]), "=r"(r[3]) : "r"(addr));
}

__device__ __forceinline__ void ldm_x4_t(uint32_t* r, uint32_t addr) {
    asm volatile("ldmatrix.sync.aligned.m8n8.x4.trans.shared.b16 {%0,%1,%2,%3}, [%4];"
                 : "=r"(r[0]), "=r"(r[1]), "=r"(r[2]), "=r"(r[3]) : "r"(addr));
}

__device__ __forceinline__ void mma_bf16(float* d, const uint32_t* a, const uint32_t* b) {
    asm volatile("mma.sync.aligned.m16n8k16.row.col.f32.bf16.bf16.f32 "
                 "{%0,%1,%2,%3}, {%4,%5,%6,%7}, {%8,%9}, {%0,%1,%2,%3};"
                 : "+f"(d[0]), "+f"(d[1]), "+f"(d[2]), "+f"(d[3])
                 : "r"(a[0]), "r"(a[1]), "r"(a[2]), "r"(a[3]),
                   "r"(b[0]), "r"(b[1]));
}

// C[M,BN] = A[M,K] @ B[K,BN]; optional row-scale (dinv), bias, relu.
template <int BN, bool BIAS, bool RELU, bool SCALE>
__global__ __launch_bounds__(256) void k_gemm_mma(
    int a_sel, int a_off, int lda,
    const float* __restrict__ B, int ldb,
    const float* __restrict__ bias,
    int c_sel, int ldc, int M, int nk) {

    constexpr int WN = BN / 4;
    constexpr int NFRAG = WN / 8;
    constexpr int LDA_S = 40;
    constexpr int LDB_S = BN + 8;

    __shared__ __align__(16) __nv_bfloat16 As[2][128][LDA_S];
    __shared__ __align__(16) __nv_bfloat16 Bs[2][32][LDB_S];

    const float* A = ((a_sel == 0) ? g_xc : g_z) + a_off;
    float* Cmat = (c_sel == 0) ? g_hW : ((c_sel == 1) ? g_z : g_z2);

    int tid = threadIdx.x;
    int wid = tid >> 5;
    int lane = tid & 31;
    int warp_m = wid >> 2;
    int warp_n = wid & 3;
    int row0 = blockIdx.x * 128;

    uint32_t asb = smem_u32(As);
    uint32_t bsb = smem_u32(Bs);

    float d[4][NFRAG][4];
    #pragma unroll
    for (int mf = 0; mf < 4; mf++)
        #pragma unroll
        for (int nf = 0; nf < NFRAG; nf++)
            #pragma unroll
            for (int j = 0; j < 4; j++) d[mf][nf][j] = 0.0f;

    for (int ck = 0; ck < nk; ck++) {
        int k0 = ck * 32;

        #pragma unroll
        for (int j = 0; j < 4; j++) {
            int i = tid + j * 256;
            int r = i >> 3;
            int c4 = (i & 7) << 2;
            float4 v = make_float4(0.f, 0.f, 0.f, 0.f);
            int gr = row0 + r;
            if (gr < M) v = *(const float4*)(A + (size_t)gr * lda + k0 + c4);
            __nv_bfloat162 h0 = __float22bfloat162_rn(make_float2(v.x, v.y));
            __nv_bfloat162 h1 = __float22bfloat162_rn(make_float2(v.z, v.w));
            float2 f0 = __bfloat1622float2(h0);
            float2 f1 = __bfloat1622float2(h1);
            __nv_bfloat162 l0 = __float22bfloat162_rn(make_float2(v.x - f0.x, v.y - f0.y));
            __nv_bfloat162 l1 = __float22bfloat162_rn(make_float2(v.z - f1.x, v.w - f1.y));
            *(__nv_bfloat162*)&As[0][r][c4]     = h0;
            *(__nv_bfloat162*)&As[0][r][c4 + 2] = h1;
            *(__nv_bfloat162*)&As[1][r][c4]     = l0;
            *(__nv_bfloat162*)&As[1][r][c4 + 2] = l1;
        }

        #pragma unroll
        for (int j = 0; j < (32 * BN / 4) / 256; j++) {
            int i = tid + j * 256;
            int kk = i / (BN / 4);
            int n4 = (i % (BN / 4)) << 2;
            float4 v = *(const float4*)(B + (size_t)(k0 + kk) * ldb + n4);
            __nv_bfloat162 h0 = __float22bfloat162_rn(make_float2(v.x, v.y));
            __nv_bfloat162 h1 = __float22bfloat162_rn(make_float2(v.z, v.w));
            float2 f0 = __bfloat1622float2(h0);
            float2 f1 = __bfloat1622float2(h1);
            __nv_bfloat162 l0 = __float22bfloat162_rn(make_float2(v.x - f0.x, v.y - f0.y));
            __nv_bfloat162 l1 = __float22bfloat162_rn(make_float2(v.z - f1.x, v.w - f1.y));
            *(__nv_bfloat162*)&Bs[0][kk][n4]     = h0;
            *(__nv_bfloat162*)&Bs[0][kk][n4 + 2] = h1;
            *(__nv_bfloat162*)&Bs[1][kk][n4]     = l0;
            *(__nv_bfloat162*)&Bs[1][kk][n4 + 2] = l1;
        }
        __syncthreads();

        #pragma unroll
        for (int ks = 0; ks < 2; ks++) {
            int kb = ks * 16;
            uint32_t a[2][4][4];
            #pragma unroll
            for (int h = 0; h < 2; h++)
                #pragma unroll
                for (int mf = 0; mf < 4; mf++) {
                    int rr = warp_m * 64 + mf * 16 + (lane & 7) + ((lane >> 3) & 1) * 8;
                    int cc = kb + (lane >> 4) * 8;
                    ldm_x4(a[h][mf],
                           asb + (uint32_t)(h * 128 * LDA_S + rr * LDA_S + cc) * 2);
                }
            uint32_t b[2][NFRAG][2];
            #pragma unroll
            for (int h = 0; h < 2; h++)
                #pragma unroll
                for (int nf2 = 0; nf2 < NFRAG / 2; nf2++) {
                    int kr = kb + ((lane >> 3) & 1) * 8 + (lane & 7);
                    int nc = warp_n * WN + nf2 * 16 + (lane >> 4) * 8;
                    uint32_t r4[4];
                    ldm_x4_t(r4, bsb + (uint32_t)(h * 32 * LDB_S + kr * LDB_S + nc) * 2);
                    b[h][nf2 * 2][0] = r4[0]; b[h][nf2 * 2][1] = r4[1];
                    b[h][nf2 * 2 + 1][0] = r4[2]; b[h][nf2 * 2 + 1][1] = r4[3];
                }
            #pragma unroll
            for (int mf = 0; mf < 4; mf++)
                #pragma unroll
                for (int nf = 0; nf < NFRAG; nf++) {
                    mma_bf16(d[mf][nf], a[0][mf], b[0][nf]);
                    mma_bf16(d[mf][nf], a[0][mf], b[1][nf]);
                    mma_bf16(d[mf][nf], a[1][mf], b[0][nf]);
                }
        }
        __syncthreads();
    }

    #pragma unroll
    for (int mf = 0; mf < 4; mf++) {
        int rbase = row0 + warp_m * 64 + mf * 16 + (lane >> 2);
        #pragma unroll
        for (int half = 0; half < 2; half++) {
            int gr = rbase + half * 8;
            if (gr < M) {
                float sc = SCALE ? g_dinv[gr] : 1.0f;
                #pragma unroll
                for (int nf = 0; nf < NFRAG; nf++) {
                    int gc = warp_n * WN + nf * 8 + (lane & 3) * 2;
                    float2 v = make_float2(d[mf][nf][half * 2], d[mf][nf][half * 2 + 1]);
                    if (SCALE) { v.x *= sc; v.y *= sc; }
                    if (BIAS) { v.x += bias[gc]; v.y += bias[gc + 1]; }
                    if (RELU) { v.x = fmaxf(v.x, 0.f); v.y = fmaxf(v.y, 0.f); }
                    *(float2*)(Cmat + (size_t)gr * ldc + gc) = v;
                }
            }
        }
    }
}

// ---------------- launch -----------------------------------------------------
extern "C" void kernel_launch(void* const* d_in, const int* in_sizes, int n_in,
                              void* d_out, int out_size) {
    const float* x      = (const float*)d_in[0];
    const int*   ei     = (const int*)d_in[1];
    const float* Wg     = (const float*)d_in[2];
    const float* bg     = (const float*)d_in[3];
    const float* ln_g   = (const float*)d_in[4];
    const float* ln_b   = (const float*)d_in[5];
    const float* mlp_W1 = (const float*)d_in[6];
    const float* mlp_b1 = (const float*)d_in[7];
    const float* mlp_W2 = (const float*)d_in[8];
    const float* mlp_b2 = (const float*)d_in[9];
    float* out = (float*)d_out;

    const int TB = 256;
    int gN   = (NN + TB - 1) / TB;
    int gE   = (EE + TB - 1) / TB;
    int gN32 = (NN * 32 + TB - 1) / TB;

    // CSR build (every call; graph-replay safe)
    k_zero_hist<<<gN, TB>>>();
    k_hist<<<gE, TB>>>(ei);
    k_scan<<<1, 1024>>>();
    k_fill<<<gE, TB>>>(ei);
    k_copy_x<<<gN32, TB>>>(x);

    int gM = (NN + 127) / 128;   // 391

    for (int i = 0; i < LLAYERS; i++) {
        // u = dinv * (h @ Wg[i])
        k_gemm_mma<128, false, false, true><<<gM, TB>>>(
            0, i * HH, XCW, Wg + (size_t)i * DD * HH, HH, nullptr,
            0, HH, NN, 4);
        k_gather_ln<<<gN32, TB>>>(bg, ln_g, ln_b, i);
    }

    // z = relu(xc @ W1 + b1)
    k_gemm_mma<128, true, true, false><<<gM, TB>>>(
        0, 0, XCW, mlp_W1, HH, mlp_b1, 1, HH, NN, 16);

    // z2 = z @ W2 + b2
    k_gemm_mma<64, true, false, false><<<gM, TB>>>(
        1, 0, HH, mlp_W2, CC, mlp_b2, 2, CC, NN, 4);

    k_softmax<<<gN32, TB>>>(out);
}

// round 5
// speedup vs baseline: 1.4250x; 1.4250x over previous
#include <cuda_runtime.h>
#include <cuda_bf16.h>
#include <cstdint>

// Problem constants
#define NN 50000
#define EE 600000
#define DD 128
#define HH 128
#define CC 64
#define LLAYERS 3
#define XCW (DD + LLAYERS * HH)   // 512

// ---------------- scratch (device globals; no runtime allocation) ----------
__device__ float g_deg[NN];
__device__ float g_dinv[NN];
__device__ float g_hW[(size_t)NN * HH];     // u = dinv * (h @ W)
__device__ float g_agg[(size_t)NN * HH];
__device__ float g_xc[(size_t)NN * XCW];
__device__ float g_z[(size_t)NN * HH];
__device__ float g_z2[(size_t)NN * CC];

// ---------------- small kernels --------------------------------------------
__global__ void k_init_deg() {
    int i = blockIdx.x * blockDim.x + threadIdx.x;
    if (i < NN) g_deg[i] = 1.0f;   // self-loop
}

__global__ void k_count_deg(const int* __restrict__ ei) {
    int e = blockIdx.x * blockDim.x + threadIdx.x;
    if (e < EE) atomicAdd(&g_deg[ei[EE + e]], 1.0f);
}

__global__ void k_dinv() {
    int i = blockIdx.x * blockDim.x + threadIdx.x;
    if (i < NN) g_dinv[i] = rsqrtf(g_deg[i]);
}

__global__ void k_copy_x(const float* __restrict__ x) {
    int idx = blockIdx.x * blockDim.x + threadIdx.x;   // float4 index
    if (idx >= NN * 32) return;
    int n = idx >> 5;
    int c = idx & 31;
    ((float4*)g_xc)[(size_t)n * (XCW / 4) + c] = ((const float4*)x)[idx];
}

// one warp per edge: agg[dst] += u[src]   (pure add; dinv folded elsewhere)
__global__ void k_scatter(const int* __restrict__ ei) {
    int t = blockIdx.x * blockDim.x + threadIdx.x;
    int w = t >> 5;
    if (w >= EE) return;
    int lane = t & 31;
    int s = __ldg(&ei[w]);
    int d = __ldg(&ei[EE + w]);
    float4 v = ((const float4*)(g_hW + (size_t)s * HH))[lane];
    float* dp = g_agg + (size_t)d * HH + lane * 4;
    asm volatile("red.global.add.v4.f32 [%0], {%1,%2,%3,%4};"
                 :: "l"(dp), "f"(v.x), "f"(v.y), "f"(v.z), "f"(v.w)
                 : "memory");
}

// one warp per node: h = relu(LN(dinv[d]*agg + bg)) -> xc[:, (1+layer)*128...]
__global__ void k_ln_relu(const float* __restrict__ bg,
                          const float* __restrict__ lng,
                          const float* __restrict__ lnb,
                          int layer) {
    int t = blockIdx.x * blockDim.x + threadIdx.x;
    int w = t >> 5;
    if (w >= NN) return;
    int lane = t & 31;
    float4 v = ((const float4*)g_agg)[(size_t)w * 32 + lane];
    float dd = g_dinv[w];
    float4 bb = ((const float4*)(bg + layer * HH))[lane];
    v.x = fmaf(v.x, dd, bb.x);
    v.y = fmaf(v.y, dd, bb.y);
    v.z = fmaf(v.z, dd, bb.z);
    v.w = fmaf(v.w, dd, bb.w);

    float s = v.x + v.y + v.z + v.w;
    #pragma unroll
    for (int o = 16; o; o >>= 1) s += __shfl_xor_sync(0xffffffffu, s, o);
    float mu = s * (1.0f / HH);

    float dx = v.x - mu, dy = v.y - mu, dz = v.z - mu, dw = v.w - mu;
    float q = dx * dx + dy * dy + dz * dz + dw * dw;
    #pragma unroll
    for (int o = 16; o; o >>= 1) q += __shfl_xor_sync(0xffffffffu, q, o);
    float inv = rsqrtf(q * (1.0f / HH) + 1e-5f);

    float4 g4 = ((const float4*)(lng + layer * HH))[lane];
    float4 b4 = ((const float4*)(lnb + layer * HH))[lane];
    float4 o4;
    o4.x = fmaxf(fmaf(g4.x * dx, inv, b4.x), 0.0f);
    o4.y = fmaxf(fmaf(g4.y * dy, inv, b4.y), 0.0f);
    o4.z = fmaxf(fmaf(g4.z * dz, inv, b4.z), 0.0f);
    o4.w = fmaxf(fmaf(g4.w * dw, inv, b4.w), 0.0f);
    ((float4*)g_xc)[(size_t)w * (XCW / 4) + (1 + layer) * 32 + lane] = o4;
}

// one warp per node: softmax over 64 (2 cols/thread)
__global__ void k_softmax(float* __restrict__ out) {
    int t = blockIdx.x * blockDim.x + threadIdx.x;
    int w = t >> 5;
    if (w >= NN) return;
    int lane = t & 31;
    float2 v = ((const float2*)g_z2)[(size_t)w * 32 + lane];
    float m = fmaxf(v.x, v.y);
    #pragma unroll
    for (int o = 16; o; o >>= 1) m = fmaxf(m, __shfl_xor_sync(0xffffffffu, m, o));
    float e0 = __expf(v.x - m);
    float e1 = __expf(v.y - m);
    float s = e0 + e1;
    #pragma unroll
    for (int o = 16; o; o >>= 1) s += __shfl_xor_sync(0xffffffffu, s, o);
    float inv = 1.0f / s;
    ((float2*)out)[(size_t)w * 32 + lane] = make_float2(e0 * inv, e1 * inv);
}

// ==================== bf16-split mma.sync GEMM ==============================
__device__ __forceinline__ uint32_t smem_u32(const void* p) {
    uint32_t a;
    asm("{ .reg .u64 t; cvta.to.shared.u64 t, %1; cvt.u32.u64 %0, t; }"
        : "=r"(a) : "l"(p));
    return a;
}

__device__ __forceinline__ void ldm_x4(uint32_t* r, uint32_t addr) {
    asm volatile("ldmatrix.sync.aligned.m8n8.x4.shared.b16 {%0,%1,%2,%3}, [%4];"
                 : "=r"(r[0]), "=r"(r[1]), "=r"(r[2]), "=r"(r[3]) : "r"(addr));
}

__device__ __forceinline__ void ldm_x4_t(uint32_t* r, uint32_t addr) {
    asm volatile("ldmatrix.sync.aligned.m8n8.x4.trans.shared.b16 {%0,%1,%2,%3}, [%4];"
                 : "=r"(r[0]), "=r"(r[1]), "=r"(r[2]), "=r"(r[3]) : "r"(addr));
}

__device__ __forceinline__ void mma_bf16(float* d, const uint32_t* a, const uint32_t* b) {
    asm volatile("mma.sync.aligned.m16n8k16.row.col.f32.bf16.bf16.f32 "
                 "{%0,%1,%2,%3}, {%4,%5,%6,%7}, {%8,%9}, {%0,%1,%2,%3};"
                 : "+f"(d[0]), "+f"(d[1]), "+f"(d[2]), "+f"(d[3])
                 : "r"(a[0]), "r"(a[1]), "r"(a[2]), "r"(a[3]),
                   "r"(b[0]), "r"(b[1]));
}

__device__ __forceinline__ void split2(float2 v, __nv_bfloat162& h, __nv_bfloat162& l) {
    h = __float22bfloat162_rn(v);
    float2 f = __bfloat1622float2(h);
    l = __float22bfloat162_rn(make_float2(v.x - f.x, v.y - f.y));
}

// C[M,BN] = A[M,K] @ B[K,BN]; register-prefetch pipelined over BK=32 chunks.
// SCALE: multiply rows by g_dinv and dual-store into g_hW AND g_agg.
template <int BN, bool BIAS, bool RELU, bool SCALE>
__global__ __launch_bounds__(256) void k_gemm_mma(
    int a_sel, int a_off, int lda,
    const float* __restrict__ B, int ldb,
    const float* __restrict__ bias,
    int c_sel, int ldc, int M, int nk) {

    constexpr int WN = BN / 4;
    constexpr int NFRAG = WN / 8;
    constexpr int NB4 = (32 * BN / 4) / 256;   // B float4s per thread: 4 or 2
    constexpr int LDA_S = 40;
    constexpr int LDB_S = BN + 8;

    __shared__ __align__(16) __nv_bfloat16 As[2][128][LDA_S];
    __shared__ __align__(16) __nv_bfloat16 Bs[2][32][LDB_S];

    const float* A = ((a_sel == 0) ? g_xc : g_z) + a_off;
    float* Cmat = (c_sel == 0) ? g_hW : ((c_sel == 1) ? g_z : g_z2);

    int tid = threadIdx.x;
    int wid = tid >> 5;
    int lane = tid & 31;
    int warp_m = wid >> 2;
    int warp_n = wid & 3;
    int row0 = blockIdx.x * 128;

    uint32_t asb = smem_u32(As);
    uint32_t bsb = smem_u32(Bs);

    float d[4][NFRAG][4];
    #pragma unroll
    for (int mf = 0; mf < 4; mf++)
        #pragma unroll
        for (int nf = 0; nf < NFRAG; nf++)
            #pragma unroll
            for (int j = 0; j < 4; j++) d[mf][nf][j] = 0.0f;

    // A element indices for this thread (4 float4s per chunk)
    float4 pa[4], pb[NB4];

    // prefetch chunk 0
    {
        #pragma unroll
        for (int j = 0; j < 4; j++) {
            int i = tid + j * 256;
            int r = i >> 3, c4 = (i & 7) << 2;
            int gr = row0 + r;
            pa[j] = make_float4(0.f, 0.f, 0.f, 0.f);
            if (gr < M) pa[j] = *(const float4*)(A + (size_t)gr * lda + c4);
        }
        #pragma unroll
        for (int j = 0; j < NB4; j++) {
            int i = tid + j * 256;
            int kk = i / (BN / 4), n4 = (i % (BN / 4)) << 2;
            pb[j] = *(const float4*)(B + (size_t)kk * ldb + n4);
        }
    }

    for (int ck = 0; ck < nk; ck++) {
        // ---- convert prefetched regs -> smem ----
        #pragma unroll
        for (int j = 0; j < 4; j++) {
            int i = tid + j * 256;
            int r = i >> 3, c4 = (i & 7) << 2;
            __nv_bfloat162 h0, l0, h1, l1;
            split2(make_float2(pa[j].x, pa[j].y), h0, l0);
            split2(make_float2(pa[j].z, pa[j].w), h1, l1);
            *(__nv_bfloat162*)&As[0][r][c4]     = h0;
            *(__nv_bfloat162*)&As[0][r][c4 + 2] = h1;
            *(__nv_bfloat162*)&As[1][r][c4]     = l0;
            *(__nv_bfloat162*)&As[1][r][c4 + 2] = l1;
        }
        #pragma unroll
        for (int j = 0; j < NB4; j++) {
            int i = tid + j * 256;
            int kk = i / (BN / 4), n4 = (i % (BN / 4)) << 2;
            __nv_bfloat162 h0, l0, h1, l1;
            split2(make_float2(pb[j].x, pb[j].y), h0, l0);
            split2(make_float2(pb[j].z, pb[j].w), h1, l1);
            *(__nv_bfloat162*)&Bs[0][kk][n4]     = h0;
            *(__nv_bfloat162*)&Bs[0][kk][n4 + 2] = h1;
            *(__nv_bfloat162*)&Bs[1][kk][n4]     = l0;
            *(__nv_bfloat162*)&Bs[1][kk][n4 + 2] = l1;
        }
        __syncthreads();

        // ---- prefetch next chunk (overlaps with compute below) ----
        if (ck + 1 < nk) {
            int k0 = (ck + 1) * 32;
            #pragma unroll
            for (int j = 0; j < 4; j++) {
                int i = tid + j * 256;
                int r = i >> 3, c4 = (i & 7) << 2;
                int gr = row0 + r;
                pa[j] = make_float4(0.f, 0.f, 0.f, 0.f);
                if (gr < M) pa[j] = *(const float4*)(A + (size_t)gr * lda + k0 + c4);
            }
            #pragma unroll
            for (int j = 0; j < NB4; j++) {
                int i = tid + j * 256;
                int kk = i / (BN / 4), n4 = (i % (BN / 4)) << 2;
                pb[j] = *(const float4*)(B + (size_t)(k0 + kk) * ldb + n4);
            }
        }

        // ---- compute: 2 k16 steps ----
        #pragma unroll
        for (int ks = 0; ks < 2; ks++) {
            int kb = ks * 16;
            uint32_t a[2][4][4];
            #pragma unroll
            for (int h = 0; h < 2; h++)
                #pragma unroll
                for (int mf = 0; mf < 4; mf++) {
                    int rr = warp_m * 64 + mf * 16 + (lane & 7) + ((lane >> 3) & 1) * 8;
                    int cc = kb + (lane >> 4) * 8;
                    ldm_x4(a[h][mf],
                           asb + (uint32_t)(h * 128 * LDA_S + rr * LDA_S + cc) * 2);
                }
            uint32_t b[2][NFRAG][2];
            #pragma unroll
            for (int h = 0; h < 2; h++)
                #pragma unroll
                for (int nf2 = 0; nf2 < NFRAG / 2; nf2++) {
                    int kr = kb + ((lane >> 3) & 1) * 8 + (lane & 7);
                    int nc = warp_n * WN + nf2 * 16 + (lane >> 4) * 8;
                    uint32_t r4[4];
                    ldm_x4_t(r4, bsb + (uint32_t)(h * 32 * LDB_S + kr * LDB_S + nc) * 2);
                    b[h][nf2 * 2][0] = r4[0]; b[h][nf2 * 2][1] = r4[1];
                    b[h][nf2 * 2 + 1][0] = r4[2]; b[h][nf2 * 2 + 1][1] = r4[3];
                }
            #pragma unroll
            for (int mf = 0; mf < 4; mf++)
                #pragma unroll
                for (int nf = 0; nf < NFRAG; nf++) {
                    mma_bf16(d[mf][nf], a[0][mf], b[0][nf]);
                    mma_bf16(d[mf][nf], a[0][mf], b[1][nf]);
                    mma_bf16(d[mf][nf], a[1][mf], b[0][nf]);
                }
        }
        __syncthreads();
    }

    // ---- epilogue ----
    #pragma unroll
    for (int mf = 0; mf < 4; mf++) {
        int rbase = row0 + warp_m * 64 + mf * 16 + (lane >> 2);
        #pragma unroll
        for (int half = 0; half < 2; half++) {
            int gr = rbase + half * 8;
            if (gr < M) {
                float sc = SCALE ? g_dinv[gr] : 1.0f;
                #pragma unroll
                for (int nf = 0; nf < NFRAG; nf++) {
                    int gc = warp_n * WN + nf * 8 + (lane & 3) * 2;
                    float2 v = make_float2(d[mf][nf][half * 2], d[mf][nf][half * 2 + 1]);
                    if (SCALE) { v.x *= sc; v.y *= sc; }
                    if (BIAS) { v.x += bias[gc]; v.y += bias[gc + 1]; }
                    if (RELU) { v.x = fmaxf(v.x, 0.f); v.y = fmaxf(v.y, 0.f); }
                    *(float2*)(Cmat + (size_t)gr * ldc + gc) = v;
                    if (SCALE)   // dual-store: init agg with self term u[d]
                        *(float2*)(g_agg + (size_t)gr * HH + gc) = v;
                }
            }
        }
    }
}

// ---------------- launch -----------------------------------------------------
extern "C" void kernel_launch(void* const* d_in, const int* in_sizes, int n_in,
                              void* d_out, int out_size) {
    const float* x      = (const float*)d_in[0];
    const int*   ei     = (const int*)d_in[1];
    const float* Wg     = (const float*)d_in[2];
    const float* bg     = (const float*)d_in[3];
    const float* ln_g   = (const float*)d_in[4];
    const float* ln_b   = (const float*)d_in[5];
    const float* mlp_W1 = (const float*)d_in[6];
    const float* mlp_b1 = (const float*)d_in[7];
    const float* mlp_W2 = (const float*)d_in[8];
    const float* mlp_b2 = (const float*)d_in[9];
    float* out = (float*)d_out;

    const int TB = 256;
    int gN   = (NN + TB - 1) / TB;
    int gE   = (EE + TB - 1) / TB;
    int gN32 = (NN * 32 + TB - 1) / TB;
    int gE32 = (EE * 32 + TB - 1) / TB;

    k_init_deg<<<gN, TB>>>();
    k_count_deg<<<gE, TB>>>(ei);
    k_dinv<<<gN, TB>>>();
    k_copy_x<<<gN32, TB>>>(x);

    int gM = (NN + 127) / 128;   // 391

    for (int i = 0; i < LLAYERS; i++) {
        // u = dinv * (h @ Wg[i]); dual-stored into g_hW and g_agg
        k_gemm_mma<128, false, false, true><<<gM, TB>>>(
            0, i * HH, XCW, Wg + (size_t)i * DD * HH, HH, nullptr,
            0, HH, NN, 4);
        k_scatter<<<gE32, TB>>>(ei);
        k_ln_relu<<<gN32, TB>>>(bg, ln_g, ln_b, i);
    }

    // z = relu(xc @ W1 + b1)
    k_gemm_mma<128, true, true, false><<<gM, TB>>>(
        0, 0, XCW, mlp_W1, HH, mlp_b1, 1, HH, NN, 16);

    // z2 = z @ W2 + b2
    k_gemm_mma<64, true, false, false><<<gM, TB>>>(
        1, 0, HH, mlp_W2, CC, mlp_b2, 2, CC, NN, 4);

    k_softmax<<<gN32, TB>>>(out);
}